// round 8
// baseline (speedup 1.0000x reference)
#include <cuda_runtime.h>
#include <cuda_bf16.h>
#include <math.h>
#include <stdint.h>

#define NN 10000
#define EE 160000

// ---------------- scratch (device globals) ----------------------------------
__device__ float g_dinv[NN];
__device__ int   g_count[NN];
__device__ int   g_fill[NN];
__device__ int   g_rowptr[NN + 1];
__device__ int   g_col[EE];
__device__ float g_ew[EE];
__device__ float g_cat[(size_t)NN * 1024];
__device__ float g_tmp[(size_t)NN * 1024];   // slabs t1,t2,t3,ua (NN*256 each)
__device__ float g_u2[NN * 256];
__device__ float g_mlp[NN * 256];            // head buffer; 'ub' scratch in layers
__device__ float g_mlp2[NN * 128];
__device__ float g_af[(size_t)NN * 1024];    // tf32-rounded GEMM input
#define WTOT 2654208
__device__ float g_wt[WTOT];                 // tf32-rounded transposed weights

__device__ __forceinline__ float gelu_f(float x) {
    return 0.5f * x * (1.0f + erff(x * 0.70710678118654752f));
}
__device__ __forceinline__ float tf32r(float x) {
    float r;
    asm("cvt.rna.tf32.f32 %0, %1;" : "=f"(r) : "f"(x));
    return r;
}
__device__ __forceinline__ uint32_t smem_u32(const void* p) {
    uint32_t a;
    asm("{ .reg .u64 t; cvta.to.shared.u64 t, %1; cvt.u32.u64 %0, t; }" : "=r"(a) : "l"(p));
    return a;
}
__device__ __forceinline__ void ldsm4(uint32_t& r0, uint32_t& r1, uint32_t& r2,
                                      uint32_t& r3, uint32_t addr) {
    asm volatile("ldmatrix.sync.aligned.m8n8.x4.shared.b16 {%0,%1,%2,%3}, [%4];"
                 : "=r"(r0), "=r"(r1), "=r"(r2), "=r"(r3) : "r"(addr));
}
__device__ __forceinline__ void mma_tf32(float* c, const uint32_t* a, const uint32_t* b) {
    asm volatile(
        "mma.sync.aligned.m16n8k8.row.col.f32.tf32.tf32.f32 "
        "{%0,%1,%2,%3}, {%4,%5,%6,%7}, {%8,%9}, {%0,%1,%2,%3};"
        : "+f"(c[0]), "+f"(c[1]), "+f"(c[2]), "+f"(c[3])
        : "r"(a[0]), "r"(a[1]), "r"(a[2]), "r"(a[3]), "r"(b[0]), "r"(b[1]));
}

// ---------------- graph preprocessing ---------------------------------------
__global__ void k_zero() {
    int i = blockIdx.x * blockDim.x + threadIdx.x;
    if (i < NN) { g_count[i] = 0; g_fill[i] = 0; }
}
__global__ void k_count(const int* __restrict__ ei) {
    int e = blockIdx.x * blockDim.x + threadIdx.x;
    if (e < EE) atomicAdd(&g_count[ei[EE + e]], 1);
}
__global__ void k_dinvk() {
    int i = blockIdx.x * blockDim.x + threadIdx.x;
    if (i < NN) g_dinv[i] = rsqrtf((float)(g_count[i] + 1));
}
__global__ void k_scan() {
    int tid = threadIdx.x, lane = tid & 31, w = tid >> 5;
    const int chunk = 10;
    int b = tid * chunk, e = min(b + chunk, NN);
    int local = 0;
    for (int i = b; i < e; i++) local += g_count[i];
    int v = local;
#pragma unroll
    for (int o = 1; o < 32; o <<= 1) {
        int t = __shfl_up_sync(0xffffffffu, v, o);
        if (lane >= o) v += t;
    }
    __shared__ int ws[32];
    if (lane == 31) ws[w] = v;
    __syncthreads();
    if (w == 0) {
        int s = ws[lane];
#pragma unroll
        for (int o = 1; o < 32; o <<= 1) {
            int t = __shfl_up_sync(0xffffffffu, s, o);
            if (lane >= o) s += t;
        }
        ws[lane] = s;
    }
    __syncthreads();
    int run = v - local + (w ? ws[w - 1] : 0);
    for (int i = b; i < e; i++) { int c = g_count[i]; g_rowptr[i] = run; run += c; }
    if (tid == 1023) g_rowptr[NN] = run;
}
__global__ void k_scatter(const int* __restrict__ ei) {
    int e = blockIdx.x * blockDim.x + threadIdx.x;
    if (e >= EE) return;
    int s = ei[e], d = ei[EE + e];
    int pos = g_rowptr[d] + atomicAdd(&g_fill[d], 1);
    g_col[pos] = s;
    g_ew[pos] = g_dinv[s] * g_dinv[d];
}

// ---------------- weight conversion (transposed, tf32-rounded) ---------------
__global__ void k_wconv(const float* __restrict__ src, float* __restrict__ dst,
                        int K, int N, size_t srcStride, size_t dstStride) {
    int m = blockIdx.y;
    int e = blockIdx.x * 256 + threadIdx.x;
    if (e >= K * N) return;
    int k = e / N, n = e % N;
    dst[m * dstStride + (size_t)n * K + k] = tf32r(src[m * srcStride + e]);
}

// ---------------- tf32 mma GEMM ----------------------------------------------
struct GOut {
    const float* a[4];
    float* p[4];
    const float* b[4];
    int ld[4];
    int act;   // 0 none, 1 gelu, 2 gelu+tf32r
};

__global__ void __launch_bounds__(128, 2) k_mma(
    const float* __restrict__ B, GOut o, int K, int bnoff) {
    extern __shared__ char smc[];
    uint32_t sb = smem_u32(smc);
    int tid = threadIdx.x, lane = tid & 31, wid = tid >> 5;
    int WM = wid >> 1, WN = wid & 1;
    int bm = blockIdx.y * 128, bn = (blockIdx.x + bnoff) * 128;
    int range = bn >> 8;
    const float* A = o.a[range];
    const int NIT = K >> 5;

    float acc[4][8][4];
#pragma unroll
    for (int i = 0; i < 4; i++)
#pragma unroll
        for (int j = 0; j < 8; j++)
#pragma unroll
            for (int r = 0; r < 4; r++) acc[i][j][r] = 0.f;

    auto LOAD = [&](int it) {
        int st = it % 3;
        uint32_t da = sb + st * 32768;
        uint32_t db = da + 16384;
        int k0 = it << 5;
#pragma unroll
        for (int i = 0; i < 8; i++) {
            int idx = i * 128 + tid;
            int row = idx >> 3, c = idx & 7;
            uint32_t so = row * 128 + ((c ^ (row & 7)) << 4);
            int ar = bm + row;
            const float* as = A + (size_t)min(ar, NN - 1) * K + k0 + c * 4;
            int sz = (ar < NN) ? 16 : 0;
            asm volatile("cp.async.cg.shared.global [%0], [%1], 16, %2;"
                         :: "r"(da + so), "l"(as), "r"(sz));
            const float* bs = B + (size_t)(bn + row) * K + k0 + c * 4;
            asm volatile("cp.async.cg.shared.global [%0], [%1], 16;"
                         :: "r"(db + so), "l"(bs));
        }
        asm volatile("cp.async.commit_group;");
    };

    LOAD(0);
    LOAD(1);
    for (int it = 0; it < NIT; it++) {
        asm volatile("cp.async.wait_group 1;");
        __syncthreads();
        if (it + 2 < NIT) LOAD(it + 2);
        int st = it % 3;
        uint32_t da = sb + st * 32768, db = da + 16384;
#pragma unroll
        for (int kk = 0; kk < 4; kk++) {
            uint32_t a[4][4], b[8][2];
#pragma unroll
            for (int mt = 0; mt < 4; mt++) {
                int row = WM * 64 + mt * 16 + (lane & 15);
                int ch = kk * 2 + (lane >> 4);
                uint32_t ad = da + row * 128 + ((ch ^ (row & 7)) << 4);
                ldsm4(a[mt][0], a[mt][1], a[mt][2], a[mt][3], ad);
            }
#pragma unroll
            for (int ng = 0; ng < 4; ng++) {
                int row = WN * 64 + ng * 16 + (lane & 7) + ((lane & 16) >> 1);
                int ch = kk * 2 + ((lane >> 3) & 1);
                uint32_t bd = db + row * 128 + ((ch ^ (row & 7)) << 4);
                ldsm4(b[2 * ng][0], b[2 * ng][1], b[2 * ng + 1][0], b[2 * ng + 1][1], bd);
            }
#pragma unroll
            for (int mt = 0; mt < 4; mt++)
#pragma unroll
                for (int nt = 0; nt < 8; nt++)
                    mma_tf32(acc[mt][nt], a[mt], b[nt]);
        }
    }

    float* D = o.p[range];
    const float* bias = o.b[range];
    int ldd = o.ld[range];
    int act = o.act;
#pragma unroll
    for (int mt = 0; mt < 4; mt++) {
        int r = bm + WM * 64 + mt * 16 + (lane >> 2);
#pragma unroll
        for (int nt = 0; nt < 8; nt++) {
            int gcol = (bn & 255) + WN * 64 + nt * 8 + ((lane & 3) << 1);
            float b0 = 0.f, b1 = 0.f;
            if (bias) { b0 = bias[gcol]; b1 = bias[gcol + 1]; }
            float v0 = acc[mt][nt][0] + b0, v1 = acc[mt][nt][1] + b1;
            float v2 = acc[mt][nt][2] + b0, v3 = acc[mt][nt][3] + b1;
            if (act) {
                v0 = gelu_f(v0); v1 = gelu_f(v1); v2 = gelu_f(v2); v3 = gelu_f(v3);
                if (act == 2) { v0 = tf32r(v0); v1 = tf32r(v1); v2 = tf32r(v2); v3 = tf32r(v3); }
            }
            if (r < NN) *(float2*)(D + (size_t)r * ldd + gcol) = make_float2(v0, v1);
            if (r + 8 < NN) *(float2*)(D + (size_t)(r + 8) * ldd + gcol) = make_float2(v2, v3);
        }
    }
}

// ---------------- fp32 SGEMM (input projection, K=84) ------------------------
template <int ACT>
__global__ void k_gemm(const float* __restrict__ A, const float* __restrict__ B,
                       const float* __restrict__ bias, float* __restrict__ C,
                       int nrows, int K, int M, int ldc) {
    __shared__ float As[16][68];
    __shared__ float Bs[16][68];
    int bm = blockIdx.y * 64, bn = blockIdx.x * 64;
    int tid = threadIdx.x;
    int tx = tid & 15, ty = tid >> 4;
    int ar = tid >> 2, ak = (tid & 3) * 4;
    int br = tid >> 4, bc = (tid & 15) * 4;
    float acc[4][4];
#pragma unroll
    for (int i = 0; i < 4; i++)
#pragma unroll
        for (int j = 0; j < 4; j++) acc[i][j] = 0.f;
    int arow = bm + ar;
    for (int k0 = 0; k0 < K; k0 += 16) {
        float a0 = 0.f, a1 = 0.f, a2 = 0.f, a3 = 0.f;
        if (arow < nrows) {
            const float* ap = A + (size_t)arow * K + k0 + ak;
            if (k0 + ak + 4 <= K) {
                float4 v = *(const float4*)ap;
                a0 = v.x; a1 = v.y; a2 = v.z; a3 = v.w;
            } else {
                int rem = K - (k0 + ak);
                if (rem > 0) a0 = ap[0];
                if (rem > 1) a1 = ap[1];
                if (rem > 2) a2 = ap[2];
                if (rem > 3) a3 = ap[3];
            }
        }
        As[ak + 0][ar] = a0; As[ak + 1][ar] = a1;
        As[ak + 2][ar] = a2; As[ak + 3][ar] = a3;
        float4 bv = make_float4(0.f, 0.f, 0.f, 0.f);
        if (k0 + br < K) bv = *(const float4*)(B + (size_t)(k0 + br) * M + bn + bc);
        *(float4*)&Bs[br][bc] = bv;
        __syncthreads();
#pragma unroll
        for (int k = 0; k < 16; k++) {
            float4 av = *(const float4*)&As[k][ty * 4];
            float4 bw = *(const float4*)&Bs[k][tx * 4];
            float a[4] = {av.x, av.y, av.z, av.w};
            float bb[4] = {bw.x, bw.y, bw.z, bw.w};
#pragma unroll
            for (int i = 0; i < 4; i++)
#pragma unroll
                for (int j = 0; j < 4; j++) acc[i][j] += a[i] * bb[j];
        }
        __syncthreads();
    }
#pragma unroll
    for (int i = 0; i < 4; i++) {
        int row = bm + ty * 4 + i;
        if (row >= nrows) continue;
#pragma unroll
        for (int j = 0; j < 4; j++) {
            int col = bn + tx * 4 + j;
            if (col >= M) continue;
            float v = acc[i][j] + bias[col];
            v = gelu_f(v);
            if (ACT == 2) v = tf32r(v);
            C[(size_t)row * ldc + col] = v;
        }
    }
}

// ---------------- SpMM: float4, 64 threads/node, 4 nodes/block ---------------
struct SpArgs {
    const float* i0; const float* i1; const float* i2;
    float* o0; float* o1; float* o2;
    const float* bias;
    int ld0, ld1, ld2;
    int rnd;
};
__global__ void __launch_bounds__(256) k_spmm(SpArgs a) {
    int y = blockIdx.y;
    const float* in = (y == 0) ? a.i0 : (y == 1) ? a.i1 : a.i2;
    float* out = (y == 0) ? a.o0 : (y == 1) ? a.o1 : a.o2;
    int ldo = (y == 0) ? a.ld0 : (y == 1) ? a.ld1 : a.ld2;
    int node = blockIdx.x * 4 + (threadIdx.x >> 6);
    int t = threadIdx.x & 63;
    if (node >= NN) return;
    const float4* in4 = (const float4*)in;
    int beg = g_rowptr[node], end = g_rowptr[node + 1];
    float di = g_dinv[node];
    float4 h = in4[(size_t)node * 64 + t];
    float w0 = di * di;
    float4 acc = make_float4(w0 * h.x, w0 * h.y, w0 * h.z, w0 * h.w);
    for (int e = beg; e < end; e++) {
        float w = __ldg(&g_ew[e]);
        float4 v = in4[(size_t)__ldg(&g_col[e]) * 64 + t];
        acc.x += w * v.x; acc.y += w * v.y; acc.z += w * v.z; acc.w += w * v.w;
    }
    if (y == 0 && a.bias) {
        const float4 b = *(const float4*)(a.bias + t * 4);
        acc.x += b.x; acc.y += b.y; acc.z += b.z; acc.w += b.w;
    }
    if (a.rnd) {
        acc.x = tf32r(acc.x); acc.y = tf32r(acc.y);
        acc.z = tf32r(acc.z); acc.w = tf32r(acc.w);
    }
    *(float4*)(out + (size_t)node * ldo + t * 4) = acc;
}

// ---------------- fused: hop3 (slab 768) + LayerNorm + GELU -> af -------------
__global__ void __launch_bounds__(256) k_spmm_ln(
    const float* __restrict__ in, const float* __restrict__ cat,
    const float* __restrict__ bias, const float* __restrict__ lg,
    const float* __restrict__ lb, float* __restrict__ af) {
    int tid = threadIdx.x;
    int t = tid & 63;
    int node = blockIdx.x * 4 + (tid >> 6);   // NN % 4 == 0
    const float4* in4 = (const float4*)in;
    int beg = g_rowptr[node], end = g_rowptr[node + 1];
    float di = g_dinv[node];
    float4 h = in4[(size_t)node * 64 + t];
    float w0 = di * di;
    float4 a3 = make_float4(w0 * h.x, w0 * h.y, w0 * h.z, w0 * h.w);
    for (int e = beg; e < end; e++) {
        float w = __ldg(&g_ew[e]);
        float4 v = in4[(size_t)__ldg(&g_col[e]) * 64 + t];
        a3.x += w * v.x; a3.y += w * v.y; a3.z += w * v.z; a3.w += w * v.w;
    }
    {
        const float4 b4 = *(const float4*)(bias + t * 4);
        a3.x += b4.x; a3.y += b4.y; a3.z += b4.z; a3.w += b4.w;
    }
    const float* crow = cat + (size_t)node * 1024;
    float4 v0 = *(const float4*)(crow + t * 4);
    float4 v1 = *(const float4*)(crow + 256 + t * 4);
    float4 v2 = *(const float4*)(crow + 512 + t * 4);
    float s = v0.x + v0.y + v0.z + v0.w + v1.x + v1.y + v1.z + v1.w +
              v2.x + v2.y + v2.z + v2.w + a3.x + a3.y + a3.z + a3.w;
    float ss = v0.x*v0.x + v0.y*v0.y + v0.z*v0.z + v0.w*v0.w +
               v1.x*v1.x + v1.y*v1.y + v1.z*v1.z + v1.w*v1.w +
               v2.x*v2.x + v2.y*v2.y + v2.z*v2.z + v2.w*v2.w +
               a3.x*a3.x + a3.y*a3.y + a3.z*a3.z + a3.w*a3.w;
    int w_ = tid >> 5, lane = tid & 31;
#pragma unroll
    for (int o = 16; o; o >>= 1) {
        s += __shfl_down_sync(0xffffffffu, s, o);
        ss += __shfl_down_sync(0xffffffffu, ss, o);
    }
    __shared__ float gs[8], gss[8];
    if (lane == 0) { gs[w_] = s; gss[w_] = ss; }
    __syncthreads();
    int wb = w_ & ~1;
    float S = gs[wb] + gs[wb + 1];
    float SS = gss[wb] + gss[wb + 1];
    float mu = S * (1.0f / 1024.0f);
    float var = SS * (1.0f / 1024.0f) - mu * mu;
    float inv = rsqrtf(var + 1e-5f);
    float* arow = af + (size_t)node * 1024;
    float vals[4][4] = {{v0.x, v0.y, v0.z, v0.w}, {v1.x, v1.y, v1.z, v1.w},
                        {v2.x, v2.y, v2.z, v2.w}, {a3.x, a3.y, a3.z, a3.w}};
#pragma unroll
    for (int r = 0; r < 4; r++) {
        int c = r * 256 + t * 4;
        float4 g4 = *(const float4*)(lg + c);
        float4 b4 = *(const float4*)(lb + c);
        float4 o4;
        o4.x = tf32r(gelu_f((vals[r][0] - mu) * inv * g4.x + b4.x));
        o4.y = tf32r(gelu_f((vals[r][1] - mu) * inv * g4.y + b4.y));
        o4.z = tf32r(gelu_f((vals[r][2] - mu) * inv * g4.z + b4.z));
        o4.w = tf32r(gelu_f((vals[r][3] - mu) * inv * g4.w + b4.w));
        *(float4*)(arow + c) = o4;
    }
}

// ---------------- LayerNorm(1024) + GELU -> af (layer 0) ---------------------
__global__ void k_ln(const float* __restrict__ h, const float* __restrict__ g,
                     const float* __restrict__ bta, float* __restrict__ af) {
    int node = blockIdx.x;
    int tid = threadIdx.x;
    const float* row = h + (size_t)node * 1024;
    float v[4];
    float s = 0.f, ss = 0.f;
#pragma unroll
    for (int i = 0; i < 4; i++) {
        v[i] = row[tid + i * 256];
        s += v[i]; ss += v[i] * v[i];
    }
    __shared__ float shs[8], shss[8];
#pragma unroll
    for (int o = 16; o; o >>= 1) {
        s += __shfl_down_sync(0xffffffffu, s, o);
        ss += __shfl_down_sync(0xffffffffu, ss, o);
    }
    int w = tid >> 5, lane = tid & 31;
    if (lane == 0) { shs[w] = s; shss[w] = ss; }
    __syncthreads();
    if (w == 0) {
        s = (lane < 8) ? shs[lane] : 0.f;
        ss = (lane < 8) ? shss[lane] : 0.f;
#pragma unroll
        for (int o = 4; o; o >>= 1) {
            s += __shfl_down_sync(0xffffffffu, s, o);
            ss += __shfl_down_sync(0xffffffffu, ss, o);
        }
        if (lane == 0) { shs[0] = s; shss[0] = ss; }
    }
    __syncthreads();
    float mu = shs[0] * (1.0f / 1024.0f);
    float var = shss[0] * (1.0f / 1024.0f) - mu * mu;
    float inv = rsqrtf(var + 1e-5f);
#pragma unroll
    for (int i = 0; i < 4; i++) {
        int c = tid + i * 256;
        float t = (v[i] - mu) * inv * g[c] + bta[c];
        af[(size_t)node * 1024 + c] = tf32r(gelu_f(t));
    }
}

// ---------------- final dot --------------------------------------------------
__global__ void k_out(const float* __restrict__ h2, const float* __restrict__ w3,
                      const float* __restrict__ b3, float* __restrict__ out, int n) {
    int gw = (blockIdx.x * blockDim.x + threadIdx.x) >> 5;
    int lane = threadIdx.x & 31;
    if (gw >= n) return;
    const float* row = h2 + (size_t)gw * 128;
    float s = 0.f;
#pragma unroll
    for (int i = 0; i < 4; i++) s += row[lane + i * 32] * w3[lane + i * 32];
#pragma unroll
    for (int o = 16; o; o >>= 1) s += __shfl_down_sync(0xffffffffu, s, o);
    if (lane == 0) out[gw] = s + b3[0];
}

// ---------------- host orchestration -----------------------------------------
template <typename T>
static T* sym(const void* s) {
    void* p = nullptr;
    cudaGetSymbolAddress(&p, s);
    return (T*)p;
}

extern "C" void kernel_launch(void* const* d_in, const int* in_sizes, int n_in,
                              void* d_out, int out_size) {
    const float* x      = (const float*)d_in[0];
    const int*   ei     = (const int*)d_in[1];
    const float* w_in   = (const float*)d_in[2];
    const float* b_in   = (const float*)d_in[3];
    const float* mh_w0  = (const float*)d_in[4];
    const float* mh_b0  = (const float*)d_in[5];
    const float* mh_w12 = (const float*)d_in[6];
    const float* mh_b12 = (const float*)d_in[7];
    const float* ln_g   = (const float*)d_in[8];
    const float* ln_b   = (const float*)d_in[9];
    const float* w1     = (const float*)d_in[10];
    const float* b1     = (const float*)d_in[11];
    const float* w2     = (const float*)d_in[12];
    const float* b2     = (const float*)d_in[13];
    const float* w3     = (const float*)d_in[14];
    const float* b3     = (const float*)d_in[15];
    float* out = (float*)d_out;

    float* cat  = sym<float>(g_cat);
    float* tmp  = sym<float>(g_tmp);
    float* u2   = sym<float>(g_u2);
    float* mlp  = sym<float>(g_mlp);
    float* mlp2 = sym<float>(g_mlp2);
    float* af   = sym<float>(g_af);
    float* wt   = sym<float>(g_wt);

    static cudaStream_t s1 = nullptr, s2 = nullptr;
    static cudaEvent_t ev[16];
    static bool init_done = false;
    if (!init_done) {
        cudaFuncSetAttribute(k_mma, cudaFuncAttributeMaxDynamicSharedMemorySize, 98304);
        cudaStreamCreateWithFlags(&s1, cudaStreamNonBlocking);
        cudaStreamCreateWithFlags(&s2, cudaStreamNonBlocking);
        for (int i = 0; i < 16; i++)
            cudaEventCreateWithFlags(&ev[i], cudaEventDisableTiming);
        init_done = true;
    }

    const size_t OFF_L0 = 0, OFF_L1 = 262144, OFF_W1 = 2359296, OFF_W2 = 2621440;

    cudaEventRecord(ev[0], 0);
    cudaStreamWaitEvent(s1, ev[0], 0);
    cudaStreamWaitEvent(s2, ev[0], 0);

    // s1: CSR build
    k_zero<<<(NN + 255) / 256, 256, 0, s1>>>();
    k_count<<<(EE + 255) / 256, 256, 0, s1>>>(ei);
    k_dinvk<<<(NN + 255) / 256, 256, 0, s1>>>();
    k_scan<<<1, 1024, 0, s1>>>();
    k_scatter<<<(EE + 255) / 256, 256, 0, s1>>>(ei);

    // s2: big weight conversions
    k_wconv<<<dim3(1024, 8), 256, 0, s2>>>(mh_w12, wt + OFF_L1, 1024, 256, 262144, 262144);
    k_wconv<<<dim3(1024, 1), 256, 0, s2>>>(w1, wt + OFF_W1, 1024, 256, 262144, 262144);
    k_wconv<<<dim3(128, 1), 256, 0, s2>>>(w2, wt + OFF_W2, 256, 128, 32768, 32768);
    cudaEventRecord(ev[1], s2);

    // main: layer-0 weights + input projection -> af
    k_wconv<<<dim3(256, 4), 256>>>(mh_w0, wt + OFF_L0, 256, 256, 65536, 65536);
    k_gemm<2><<<dim3(4, (NN + 63) / 64), 256>>>(x, w_in, b_in, af, NN, 84, 256, 256);
    cudaEventRecord(ev[2], 0);

    float* t1 = tmp;
    float* t2 = tmp + (size_t)NN * 256;
    float* t3 = tmp + (size_t)2 * NN * 256;
    float* ua = tmp + (size_t)3 * NN * 256;
    float* ub = mlp;                    // scratch during layers; head buffer later
    const int SPG = NN / 4;

    // ---- layer 0: hops on s1, per-range GEMMs on main as hops complete ----
    cudaStreamWaitEvent(s1, ev[2], 0);
    {
        SpArgs p1{af, nullptr, nullptr, t1, nullptr, nullptr, nullptr, 256, 0, 0, 1};
        k_spmm<<<dim3(SPG, 1), 256, 0, s1>>>(p1);
        cudaEventRecord(ev[3], s1);
        SpArgs p2{t1, nullptr, nullptr, t2, nullptr, nullptr, nullptr, 256, 0, 0, 1};
        k_spmm<<<dim3(SPG, 1), 256, 0, s1>>>(p2);
        cudaEventRecord(ev[4], s1);
        SpArgs p3{t2, nullptr, nullptr, t3, nullptr, nullptr, nullptr, 256, 0, 0, 1};
        k_spmm<<<dim3(SPG, 1), 256, 0, s1>>>(p3);
        cudaEventRecord(ev[5], s1);

        GOut o;
        o.a[0] = af; o.a[1] = t1; o.a[2] = t2; o.a[3] = t3;
        o.p[0] = cat; o.p[1] = cat + 256; o.p[2] = cat + 512; o.p[3] = cat + 768;
        o.b[0] = mh_b0; o.b[1] = mh_b0 + 256; o.b[2] = mh_b0 + 512; o.b[3] = mh_b0 + 768;
        o.ld[0] = o.ld[1] = o.ld[2] = o.ld[3] = 1024;
        o.act = 0;
        k_mma<<<dim3(2, 79), 128, 98304>>>(wt + OFF_L0, o, 256, 0);
        cudaStreamWaitEvent(0, ev[3], 0);
        k_mma<<<dim3(2, 79), 128, 98304>>>(wt + OFF_L0, o, 256, 2);
        cudaStreamWaitEvent(0, ev[4], 0);
        k_mma<<<dim3(2, 79), 128, 98304>>>(wt + OFF_L0, o, 256, 4);
        cudaStreamWaitEvent(0, ev[5], 0);
        k_mma<<<dim3(2, 79), 128, 98304>>>(wt + OFF_L0, o, 256, 6);
        k_ln<<<NN, 256>>>(cat, ln_g, ln_b, af);
    }

    cudaStreamWaitEvent(0, ev[1], 0);   // big weights ready

    // ---- layers 1,2: dependency-pipelined ----
    // main: r3 GEMM -> [s1: t3->ua->u2 chain]  then r1+r2 GEMM -> h1 -> h2
    // s2:   r0 GEMM -> cat[0:256]
    // join: fused k_spmm_ln(u2)
    auto LAYER = [&](size_t woff, const float* bb, const float* lg, const float* lb,
                     int e0, int e1, int e2, int e3) {
        GOut o;
        o.a[0] = o.a[1] = o.a[2] = o.a[3] = af;
        o.p[0] = cat; o.p[1] = t1; o.p[2] = t2; o.p[3] = t3;
        o.b[0] = bb;  o.b[1] = nullptr; o.b[2] = nullptr; o.b[3] = nullptr;
        o.ld[0] = 1024; o.ld[1] = 256; o.ld[2] = 256; o.ld[3] = 256;
        o.act = 0;
        cudaEventRecord(ev[e0], 0);
        cudaStreamWaitEvent(s2, ev[e0], 0);
        k_mma<<<dim3(2, 79), 128, 98304, s2>>>(wt + woff, o, 1024, 0);   // r0 -> cat
        cudaEventRecord(ev[e1], s2);

        k_mma<<<dim3(2, 79), 128, 98304>>>(wt + woff, o, 1024, 6);       // r3 -> t3
        cudaEventRecord(ev[e2], 0);
        cudaStreamWaitEvent(s1, ev[e2], 0);
        SpArgs q1{t3, nullptr, nullptr, ua, nullptr, nullptr, nullptr, 256, 0, 0, 0};
        k_spmm<<<dim3(SPG, 1), 256, 0, s1>>>(q1);
        SpArgs q2{ua, nullptr, nullptr, u2, nullptr, nullptr, nullptr, 256, 0, 0, 0};
        k_spmm<<<dim3(SPG, 1), 256, 0, s1>>>(q2);
        cudaEventRecord(ev[e3], s1);

        k_mma<<<dim3(4, 79), 128, 98304>>>(wt + woff, o, 1024, 2);       // r1,r2
        SpArgs h1{t1, t2, nullptr, cat + 256, ub, nullptr, bb + 256, 1024, 256, 0, 0};
        k_spmm<<<dim3(SPG, 2), 256>>>(h1);
        SpArgs h2{ub, nullptr, nullptr, cat + 512, nullptr, nullptr, bb + 512, 1024, 0, 0, 0};
        k_spmm<<<dim3(SPG, 1), 256>>>(h2);
        cudaStreamWaitEvent(0, ev[e1], 0);
        cudaStreamWaitEvent(0, ev[e3], 0);
        k_spmm_ln<<<SPG, 256>>>(u2, cat, bb + 768, lg, lb, af);
    };

    LAYER(OFF_L1,              mh_b12,        ln_g + 1024, ln_b + 1024, 6, 7, 8, 9);
    LAYER(OFF_L1 + 4 * 262144, mh_b12 + 1024, ln_g + 2048, ln_b + 2048, 10, 11, 12, 13);

    // ---- head MLP ----
    GOut oh;
    oh.a[0] = af; oh.a[1] = oh.a[2] = oh.a[3] = nullptr;
    oh.p[0] = mlp; oh.p[1] = oh.p[2] = oh.p[3] = nullptr;
    oh.b[0] = b1;  oh.b[1] = oh.b[2] = oh.b[3] = nullptr;
    oh.ld[0] = 256; oh.ld[1] = oh.ld[2] = oh.ld[3] = 0;
    oh.act = 2;
    k_mma<<<dim3(2, 79), 128, 98304>>>(wt + OFF_W1, oh, 1024, 0);

    GOut o2;
    o2.a[0] = mlp; o2.a[1] = o2.a[2] = o2.a[3] = nullptr;
    o2.p[0] = mlp2; o2.p[1] = o2.p[2] = o2.p[3] = nullptr;
    o2.b[0] = b2;   o2.b[1] = o2.b[2] = o2.b[3] = nullptr;
    o2.ld[0] = 128; o2.ld[1] = o2.ld[2] = o2.ld[3] = 0;
    o2.act = 1;
    k_mma<<<dim3(1, 79), 128, 98304>>>(wt + OFF_W2, o2, 256, 0);

    k_out<<<(NN * 32 + 255) / 256, 256>>>(mlp2, w3, b3, out, NN);
}